// round 3
// baseline (speedup 1.0000x reference)
#include <cuda_runtime.h>
#include <cstdint>

#define BB 4
#define CK 64
#define NKEY 8192
#define MQ 1024
#define CVAL 512
#define BM 32
#define BN 32
#define NTHREADS 256
#define NCHUNK (NKEY / BN)

// Shared memory layout (float offsets)
#define SOFF_QS2  0                     // 64*32*2  (q duplicated pairs)
#define SOFF_KS   4096                  // 2 * 64*32 (double buffered)
#define SOFF_PS   8192                  // 32 rows * 36
#define SOFF_ASQ  9344                  // 2 * 32
#define SOFF_QSQ  9408                  // 32
#define SOFF_RED  9440                  // 256
#define SOFF_SUM  9696                  // 32
#define SOFF_VS   9728                  // 2 * 512*36 (double buffered)
#define SMEM_FLOATS (9728 + 2*512*36)
#define SMEM_BYTES  (SMEM_FLOATS * 4)

__device__ float g_asq[BB * NKEY];

__global__ void asq_kernel(const float* __restrict__ mk) {
    int i = blockIdx.x * blockDim.x + threadIdx.x;
    if (i >= BB * NKEY) return;
    int b = i >> 13;
    int n = i & (NKEY - 1);
    const float* p = mk + ((size_t)b * CK) * NKEY + n;
    float s = 0.f;
#pragma unroll 8
    for (int c = 0; c < CK; ++c) { float v = p[(size_t)c * NKEY]; s = fmaf(v, v, s); }
    g_asq[i] = s;
}

#define FMA2(d, a, bb) asm("fma.rn.f32x2 %0, %1, %2, %0;" : "+l"(d) : "l"(a), "l"(bb))
#define PACK2(d, lo, hi) asm("mov.b64 %0, {%1, %2};" : "=l"(d) : "r"(__float_as_uint(lo)), "r"(__float_as_uint(hi)))

__device__ __forceinline__ void cpa16(const void* s, const void* g) {
    uint32_t sa = (uint32_t)__cvta_generic_to_shared(s);
    asm volatile("cp.async.cg.shared.global [%0], [%1], 16;" :: "r"(sa), "l"(g) : "memory");
}
#define CP_COMMIT asm volatile("cp.async.commit_group;" ::: "memory")
#define CP_WAIT0  asm volatile("cp.async.wait_group 0;" ::: "memory")

#define PREFETCH(n0, pbuf) do {                                               \
    _Pragma("unroll")                                                         \
    for (int k = 0; k < 2; ++k) {                                             \
        int i = tid + k * NTHREADS; int c = i >> 3, g = (i & 7) * 4;          \
        cpa16(S_KS + (pbuf) * 2048 + c * 32 + g,                              \
              mk_b + (size_t)c * NKEY + (n0) + g);                            \
    }                                                                         \
    _Pragma("unroll")                                                         \
    for (int k = 0; k < 16; ++k) {                                            \
        int i = tid + k * NTHREADS; int c = i >> 3, g = (i & 7) * 4;          \
        cpa16(S_VS + (pbuf) * 18432 + c * 36 + g,                             \
              mv_b + (size_t)c * NKEY + (n0) + g);                            \
    }                                                                         \
    if (tid < 8) cpa16(S_ASQ + (pbuf) * 32 + tid * 4,                         \
                       g_asq + b * NKEY + (n0) + tid * 4);                    \
    CP_COMMIT;                                                                \
} while (0)

__global__ void __launch_bounds__(NTHREADS, 1)
mr_main_kernel(const float* __restrict__ mk, const float* __restrict__ qk,
               const float* __restrict__ mv, float* __restrict__ out)
{
    extern __shared__ float sm[];
    float* S_QS2 = sm + SOFF_QS2;
    float* S_KS  = sm + SOFF_KS;
    float* S_PS  = sm + SOFF_PS;
    float* S_ASQ = sm + SOFF_ASQ;
    float* S_QSQ = sm + SOFF_QSQ;
    float* S_RED = sm + SOFF_RED;
    float* S_SUM = sm + SOFF_SUM;
    float* S_VS  = sm + SOFF_VS;

    const int tid = threadIdx.x;
    const int b   = blockIdx.y;
    const int m0  = blockIdx.x * BM;

    const float* mk_b = mk + ((size_t)b * CK) * NKEY;
    const float* mv_b = mv + ((size_t)b * CVAL) * NKEY;

    // ---- load Q block as duplicated pairs: QS2[c][m] = (q,q) ----
#pragma unroll
    for (int k = 0; k < 2; ++k) {
        int i = tid + k * NTHREADS;
        int c = i >> 3, g = (i & 7) * 4;
        float4 v = *(const float4*)(qk + ((size_t)(b * CK + c)) * MQ + m0 + g);
        unsigned long long* dst = (unsigned long long*)(S_QS2) + (c * 32 + g);
        unsigned long long d;
        PACK2(d, v.x, v.x); dst[0] = d;
        PACK2(d, v.y, v.y); dst[1] = d;
        PACK2(d, v.z, v.z); dst[2] = d;
        PACK2(d, v.w, v.w); dst[3] = d;
    }
    __syncthreads();
    if (tid < 32) {
        float s = 0.f;
#pragma unroll 8
        for (int c = 0; c < CK; ++c) { float q = S_QS2[(c * 32 + tid) * 2]; s = fmaf(q, q, s); }
        S_QSQ[tid] = s;
    }

    // thread roles
    const int nnb   = (tid & 7) * 4;   // logit phase: 4 keys
    const int lm    = tid >> 3;        //              1 query
    const int sm_m  = tid & 31;        // sumexp partial
    const int sm_n  = (tid >> 5) * 4;
    const int mgrp  = tid & 3;         // accumulate: 8 m
    const int cgrp  = tid >> 2;        //             8 c (stride 64)
    const int m_base = mgrp * 8;

    unsigned long long acc[8][4];
#pragma unroll
    for (int i = 0; i < 8; ++i)
#pragma unroll
        for (int j = 0; j < 4; ++j) acc[i][j] = 0ull;
    float se = 0.f;

    // prologue: stage chunk 0
    PREFETCH(0, 0);
    CP_WAIT0;
    __syncthreads();

    for (int it = 0; it < NCHUNK; ++it) {
        const int buf = it & 1;
        const float* S_KSb = S_KS + buf * 2048;
        const float* S_VSb = S_VS + buf * 18432;
        const float* S_ASQb = S_ASQ + buf * 32;

        // prefetch next chunk into the other buffer (overlaps with compute)
        if (it + 1 < NCHUNK) PREFETCH((it + 1) * BN, buf ^ 1);

        // ---- logits + exp (packed f32x2): 4 keys x 1 query per thread ----
        {
            unsigned long long d01 = 0ull, d23 = 0ull;
            const unsigned long long* qdup = (const unsigned long long*)(S_QS2) + lm;
#pragma unroll 16
            for (int c = 0; c < CK; ++c) {
                ulonglong2 kk = *(const ulonglong2*)(S_KSb + c * 32 + nnb);
                unsigned long long q2 = qdup[c * 32];
                FMA2(d01, kk.x, q2);
                FMA2(d23, kk.y, q2);
            }
            unsigned int u0, u1, u2, u3;
            asm("mov.b64 {%0, %1}, %2;" : "=r"(u0), "=r"(u1) : "l"(d01));
            asm("mov.b64 {%0, %1}, %2;" : "=r"(u2), "=r"(u3) : "l"(d23));
            float qq = S_QSQ[lm];
            S_PS[(nnb + 0) * 36 + lm] = __expf((2.f * __uint_as_float(u0) - S_ASQb[nnb + 0] - qq) * 0.125f);
            S_PS[(nnb + 1) * 36 + lm] = __expf((2.f * __uint_as_float(u1) - S_ASQb[nnb + 1] - qq) * 0.125f);
            S_PS[(nnb + 2) * 36 + lm] = __expf((2.f * __uint_as_float(u2) - S_ASQb[nnb + 2] - qq) * 0.125f);
            S_PS[(nnb + 3) * 36 + lm] = __expf((2.f * __uint_as_float(u3) - S_ASQb[nnb + 3] - qq) * 0.125f);
        }
        __syncthreads();

        // ---- sumexp partials ----
        se += S_PS[(sm_n + 0) * 36 + sm_m] + S_PS[(sm_n + 1) * 36 + sm_m]
            + S_PS[(sm_n + 2) * 36 + sm_m] + S_PS[(sm_n + 3) * 36 + sm_m];

        // ---- PV accumulate: acc[c][m] += v[c][nn] * p[nn][m] (f32x2 m-pairs) ----
#pragma unroll 1
        for (int blk = 0; blk < 8; ++blk) {
            const int nn0 = blk * 4;
            unsigned long long p2[4][4];
#pragma unroll
            for (int j = 0; j < 4; ++j) {
                const float* pp = S_PS + (nn0 + j) * 36 + m_base;
                ulonglong2 t0 = *(const ulonglong2*)(pp);
                ulonglong2 t1 = *(const ulonglong2*)(pp + 4);
                p2[j][0] = t0.x; p2[j][1] = t0.y; p2[j][2] = t1.x; p2[j][3] = t1.y;
            }
#pragma unroll
            for (int ci = 0; ci < 8; ++ci) {
                const float4 v = *(const float4*)(S_VSb + (cgrp + ci * 64) * 36 + nn0);
                unsigned long long vv;
                PACK2(vv, v.x, v.x);
                FMA2(acc[ci][0], vv, p2[0][0]); FMA2(acc[ci][1], vv, p2[0][1]);
                FMA2(acc[ci][2], vv, p2[0][2]); FMA2(acc[ci][3], vv, p2[0][3]);
                PACK2(vv, v.y, v.y);
                FMA2(acc[ci][0], vv, p2[1][0]); FMA2(acc[ci][1], vv, p2[1][1]);
                FMA2(acc[ci][2], vv, p2[1][2]); FMA2(acc[ci][3], vv, p2[1][3]);
                PACK2(vv, v.z, v.z);
                FMA2(acc[ci][0], vv, p2[2][0]); FMA2(acc[ci][1], vv, p2[2][1]);
                FMA2(acc[ci][2], vv, p2[2][2]); FMA2(acc[ci][3], vv, p2[2][3]);
                PACK2(vv, v.w, v.w);
                FMA2(acc[ci][0], vv, p2[3][0]); FMA2(acc[ci][1], vv, p2[3][1]);
                FMA2(acc[ci][2], vv, p2[3][2]); FMA2(acc[ci][3], vv, p2[3][3]);
            }
        }

        // staged data for chunk it+1 complete; barrier also republishes PS/VS buffers
        CP_WAIT0;
        __syncthreads();
    }

    // ---- reduce sumexp across the 8 nn-slot groups ----
    S_RED[(tid >> 5) * 32 + (tid & 31)] = se;
    __syncthreads();
    if (tid < 32) {
        float s = 0.f;
#pragma unroll
        for (int g = 0; g < 8; ++g) s += S_RED[g * 32 + tid];
        S_SUM[tid] = 1.0f / s;
    }
    __syncthreads();

    float r[8];
#pragma unroll
    for (int k = 0; k < 8; ++k) r[k] = S_SUM[m_base + k];

#pragma unroll
    for (int ci = 0; ci < 8; ++ci) {
        int c = cgrp + ci * 64;
        float* po = out + ((size_t)(b * CVAL + c)) * MQ + m0 + m_base;
#pragma unroll
        for (int mp = 0; mp < 4; ++mp) {
            unsigned int u0, u1;
            asm("mov.b64 {%0, %1}, %2;" : "=r"(u0), "=r"(u1) : "l"(acc[ci][mp]));
            float2 o;
            o.x = __uint_as_float(u0) * r[2 * mp + 0];
            o.y = __uint_as_float(u1) * r[2 * mp + 1];
            *(float2*)(po + 2 * mp) = o;
        }
    }
}

extern "C" void kernel_launch(void* const* d_in, const int* in_sizes, int n_in,
                              void* d_out, int out_size) {
    const float* mk = (const float*)d_in[0];
    const float* qk = (const float*)d_in[1];
    const float* mv = (const float*)d_in[2];
    float* out = (float*)d_out;

    asq_kernel<<<(BB * NKEY + 255) / 256, 256>>>(mk);

    cudaFuncSetAttribute(mr_main_kernel,
                         cudaFuncAttributeMaxDynamicSharedMemorySize, SMEM_BYTES);
    dim3 grid(MQ / BM, BB);
    mr_main_kernel<<<grid, NTHREADS, SMEM_BYTES>>>(mk, qk, mv, out);
}

// round 4
// speedup vs baseline: 1.0006x; 1.0006x over previous
#include <cuda_runtime.h>
#include <cstdint>

#define BB 4
#define CK 64
#define NKEY 8192
#define MQ 1024
#define CVAL 512
#define BM 32
#define BN 32
#define NTHREADS 256
#define NCHUNK (NKEY / BN)

// Shared memory layout (float offsets)
#define SOFF_QS2  0                     // 64*32*2  (q duplicated pairs)
#define SOFF_KS   4096                  // 2 * 64*32 (double buffered)
#define SOFF_PS   8192                  // 32 rows * 36
#define SOFF_ASQ  9344                  // 2 * 32
#define SOFF_QSQ  9408                  // 32
#define SOFF_RED  9440                  // 256
#define SOFF_SUM  9696                  // 32
#define SOFF_VS   9728                  // 2 * 512*36 (double buffered)
#define SMEM_FLOATS (9728 + 2*512*36)
#define SMEM_BYTES  (SMEM_FLOATS * 4)

__device__ float g_asq[BB * NKEY];

__global__ void asq_kernel(const float* __restrict__ mk) {
    int i = blockIdx.x * blockDim.x + threadIdx.x;
    if (i >= BB * NKEY) return;
    int b = i >> 13;
    int n = i & (NKEY - 1);
    const float* p = mk + ((size_t)b * CK) * NKEY + n;
    float s = 0.f;
#pragma unroll 8
    for (int c = 0; c < CK; ++c) { float v = p[(size_t)c * NKEY]; s = fmaf(v, v, s); }
    g_asq[i] = s;
}

#define FMA2(d, a, bb) asm("fma.rn.f32x2 %0, %1, %2, %0;" : "+l"(d) : "l"(a), "l"(bb))
#define PACK2(d, lo, hi) asm("mov.b64 %0, {%1, %2};" : "=l"(d) : "r"(__float_as_uint(lo)), "r"(__float_as_uint(hi)))

__device__ __forceinline__ void cpa16(const void* s, const void* g) {
    uint32_t sa = (uint32_t)__cvta_generic_to_shared(s);
    asm volatile("cp.async.cg.shared.global [%0], [%1], 16;" :: "r"(sa), "l"(g) : "memory");
}
#define CP_COMMIT asm volatile("cp.async.commit_group;" ::: "memory")
#define CP_WAIT0  asm volatile("cp.async.wait_group 0;" ::: "memory")

#define PREFETCH(n0, pbuf) do {                                               \
    _Pragma("unroll")                                                         \
    for (int k = 0; k < 2; ++k) {                                             \
        int i = tid + k * NTHREADS; int c = i >> 3, g = (i & 7) * 4;          \
        cpa16(S_KS + (pbuf) * 2048 + c * 32 + g,                              \
              mk_b + (size_t)c * NKEY + (n0) + g);                            \
    }                                                                         \
    _Pragma("unroll")                                                         \
    for (int k = 0; k < 16; ++k) {                                            \
        int i = tid + k * NTHREADS; int c = i >> 3, g = (i & 7) * 4;          \
        cpa16(S_VS + (pbuf) * 18432 + c * 36 + g,                             \
              mv_b + (size_t)c * NKEY + (n0) + g);                            \
    }                                                                         \
    if (tid < 8) cpa16(S_ASQ + (pbuf) * 32 + tid * 4,                         \
                       g_asq + b * NKEY + (n0) + tid * 4);                    \
    CP_COMMIT;                                                                \
} while (0)

__global__ void __launch_bounds__(NTHREADS, 1)
mr_main_kernel(const float* __restrict__ mk, const float* __restrict__ qk,
               const float* __restrict__ mv, float* __restrict__ out)
{
    extern __shared__ float sm[];
    float* S_QS2 = sm + SOFF_QS2;
    float* S_KS  = sm + SOFF_KS;
    float* S_PS  = sm + SOFF_PS;
    float* S_ASQ = sm + SOFF_ASQ;
    float* S_QSQ = sm + SOFF_QSQ;
    float* S_RED = sm + SOFF_RED;
    float* S_SUM = sm + SOFF_SUM;
    float* S_VS  = sm + SOFF_VS;

    const int tid = threadIdx.x;
    const int b   = blockIdx.y;
    const int m0  = blockIdx.x * BM;

    const float* mk_b = mk + ((size_t)b * CK) * NKEY;
    const float* mv_b = mv + ((size_t)b * CVAL) * NKEY;

    // ---- load Q block as duplicated pairs: QS2[c][m] = (q,q) ----
#pragma unroll
    for (int k = 0; k < 2; ++k) {
        int i = tid + k * NTHREADS;
        int c = i >> 3, g = (i & 7) * 4;
        float4 v = *(const float4*)(qk + ((size_t)(b * CK + c)) * MQ + m0 + g);
        unsigned long long* dst = (unsigned long long*)(S_QS2) + (c * 32 + g);
        unsigned long long d;
        PACK2(d, v.x, v.x); dst[0] = d;
        PACK2(d, v.y, v.y); dst[1] = d;
        PACK2(d, v.z, v.z); dst[2] = d;
        PACK2(d, v.w, v.w); dst[3] = d;
    }
    __syncthreads();
    if (tid < 32) {
        float s = 0.f;
#pragma unroll 8
        for (int c = 0; c < CK; ++c) { float q = S_QS2[(c * 32 + tid) * 2]; s = fmaf(q, q, s); }
        S_QSQ[tid] = s;
    }

    // thread roles
    const int nnb   = (tid & 7) * 4;   // logit phase: 4 keys
    const int lm    = tid >> 3;        //              1 query
    const int sm_m  = tid & 31;        // sumexp partial
    const int sm_n  = (tid >> 5) * 4;
    const int mgrp  = tid & 3;         // accumulate: 8 m
    const int cgrp  = tid >> 2;        //             8 c (stride 64)
    const int m_base = mgrp * 8;

    unsigned long long acc[8][4];
#pragma unroll
    for (int i = 0; i < 8; ++i)
#pragma unroll
        for (int j = 0; j < 4; ++j) acc[i][j] = 0ull;
    float se = 0.f;

    // prologue: stage chunk 0
    PREFETCH(0, 0);
    CP_WAIT0;
    __syncthreads();

    for (int it = 0; it < NCHUNK; ++it) {
        const int buf = it & 1;
        const float* S_KSb = S_KS + buf * 2048;
        const float* S_VSb = S_VS + buf * 18432;
        const float* S_ASQb = S_ASQ + buf * 32;

        // prefetch next chunk into the other buffer (overlaps with compute)
        if (it + 1 < NCHUNK) PREFETCH((it + 1) * BN, buf ^ 1);

        // ---- logits + exp (packed f32x2): 4 keys x 1 query per thread ----
        {
            unsigned long long d01 = 0ull, d23 = 0ull;
            const unsigned long long* qdup = (const unsigned long long*)(S_QS2) + lm;
#pragma unroll 16
            for (int c = 0; c < CK; ++c) {
                ulonglong2 kk = *(const ulonglong2*)(S_KSb + c * 32 + nnb);
                unsigned long long q2 = qdup[c * 32];
                FMA2(d01, kk.x, q2);
                FMA2(d23, kk.y, q2);
            }
            unsigned int u0, u1, u2, u3;
            asm("mov.b64 {%0, %1}, %2;" : "=r"(u0), "=r"(u1) : "l"(d01));
            asm("mov.b64 {%0, %1}, %2;" : "=r"(u2), "=r"(u3) : "l"(d23));
            float qq = S_QSQ[lm];
            S_PS[(nnb + 0) * 36 + lm] = __expf((2.f * __uint_as_float(u0) - S_ASQb[nnb + 0] - qq) * 0.125f);
            S_PS[(nnb + 1) * 36 + lm] = __expf((2.f * __uint_as_float(u1) - S_ASQb[nnb + 1] - qq) * 0.125f);
            S_PS[(nnb + 2) * 36 + lm] = __expf((2.f * __uint_as_float(u2) - S_ASQb[nnb + 2] - qq) * 0.125f);
            S_PS[(nnb + 3) * 36 + lm] = __expf((2.f * __uint_as_float(u3) - S_ASQb[nnb + 3] - qq) * 0.125f);
        }
        __syncthreads();

        // ---- sumexp partials ----
        se += S_PS[(sm_n + 0) * 36 + sm_m] + S_PS[(sm_n + 1) * 36 + sm_m]
            + S_PS[(sm_n + 2) * 36 + sm_m] + S_PS[(sm_n + 3) * 36 + sm_m];

        // ---- PV accumulate: acc[c][m] += v[c][nn] * p[nn][m] (f32x2 m-pairs) ----
#pragma unroll 1
        for (int blk = 0; blk < 8; ++blk) {
            const int nn0 = blk * 4;
            unsigned long long p2[4][4];
#pragma unroll
            for (int j = 0; j < 4; ++j) {
                const float* pp = S_PS + (nn0 + j) * 36 + m_base;
                ulonglong2 t0 = *(const ulonglong2*)(pp);
                ulonglong2 t1 = *(const ulonglong2*)(pp + 4);
                p2[j][0] = t0.x; p2[j][1] = t0.y; p2[j][2] = t1.x; p2[j][3] = t1.y;
            }
#pragma unroll
            for (int ci = 0; ci < 8; ++ci) {
                const float4 v = *(const float4*)(S_VSb + (cgrp + ci * 64) * 36 + nn0);
                unsigned long long vv;
                PACK2(vv, v.x, v.x);
                FMA2(acc[ci][0], vv, p2[0][0]); FMA2(acc[ci][1], vv, p2[0][1]);
                FMA2(acc[ci][2], vv, p2[0][2]); FMA2(acc[ci][3], vv, p2[0][3]);
                PACK2(vv, v.y, v.y);
                FMA2(acc[ci][0], vv, p2[1][0]); FMA2(acc[ci][1], vv, p2[1][1]);
                FMA2(acc[ci][2], vv, p2[1][2]); FMA2(acc[ci][3], vv, p2[1][3]);
                PACK2(vv, v.z, v.z);
                FMA2(acc[ci][0], vv, p2[2][0]); FMA2(acc[ci][1], vv, p2[2][1]);
                FMA2(acc[ci][2], vv, p2[2][2]); FMA2(acc[ci][3], vv, p2[2][3]);
                PACK2(vv, v.w, v.w);
                FMA2(acc[ci][0], vv, p2[3][0]); FMA2(acc[ci][1], vv, p2[3][1]);
                FMA2(acc[ci][2], vv, p2[3][2]); FMA2(acc[ci][3], vv, p2[3][3]);
            }
        }

        // staged data for chunk it+1 complete; barrier also republishes PS/VS buffers
        CP_WAIT0;
        __syncthreads();
    }

    // ---- reduce sumexp across the 8 nn-slot groups ----
    S_RED[(tid >> 5) * 32 + (tid & 31)] = se;
    __syncthreads();
    if (tid < 32) {
        float s = 0.f;
#pragma unroll
        for (int g = 0; g < 8; ++g) s += S_RED[g * 32 + tid];
        S_SUM[tid] = 1.0f / s;
    }
    __syncthreads();

    float r[8];
#pragma unroll
    for (int k = 0; k < 8; ++k) r[k] = S_SUM[m_base + k];

#pragma unroll
    for (int ci = 0; ci < 8; ++ci) {
        int c = cgrp + ci * 64;
        float* po = out + ((size_t)(b * CVAL + c)) * MQ + m0 + m_base;
#pragma unroll
        for (int mp = 0; mp < 4; ++mp) {
            unsigned int u0, u1;
            asm("mov.b64 {%0, %1}, %2;" : "=r"(u0), "=r"(u1) : "l"(acc[ci][mp]));
            float2 o;
            o.x = __uint_as_float(u0) * r[2 * mp + 0];
            o.y = __uint_as_float(u1) * r[2 * mp + 1];
            *(float2*)(po + 2 * mp) = o;
        }
    }
}

extern "C" void kernel_launch(void* const* d_in, const int* in_sizes, int n_in,
                              void* d_out, int out_size) {
    const float* mk = (const float*)d_in[0];
    const float* qk = (const float*)d_in[1];
    const float* mv = (const float*)d_in[2];
    float* out = (float*)d_out;

    asq_kernel<<<(BB * NKEY + 255) / 256, 256>>>(mk);

    cudaFuncSetAttribute(mr_main_kernel,
                         cudaFuncAttributeMaxDynamicSharedMemorySize, SMEM_BYTES);
    dim3 grid(MQ / BM, BB);
    mr_main_kernel<<<grid, NTHREADS, SMEM_BYTES>>>(mk, qk, mv, out);
}

// round 7
// speedup vs baseline: 4.2306x; 4.2280x over previous
#include <cuda_runtime.h>
#include <cuda_fp16.h>
#include <cstdint>

#define BB 4
#define CK 64
#define NKEY 8192
#define MQ 1024
#define CVAL 512
#define BM 32
#define CHUNK 64
#define NCH (NKEY/CHUNK)
#define NT 256
#define SHIFT 10.0f

__device__ __half g_kth[(size_t)BB*NKEY*CK];   // [b][n][c] hi
__device__ __half g_ktl[(size_t)BB*NKEY*CK];   // [b][n][c] lo
__device__ __half g_qth[(size_t)BB*CK*MQ];     // [b][c][m] hi
__device__ __half g_qtl[(size_t)BB*CK*MQ];     // [b][c][m] lo
__device__ __half g_vhi[(size_t)BB*CVAL*NKEY]; // [b][c][n] hi
__device__ float  g_asq[BB*NKEY];
__device__ float  g_qsq[BB*MQ];

// smem byte offsets
#define SM_ASQ 0        /* 2*256 */
#define SM_QSQ 512
#define SM_INV 640
#define SM_SE  768
#define SM_QH  1024     /* 64 rows * 80B */
#define SM_QL  6144
#define SM_PH  11264    /* 64 rows * 80B */
#define SM_PL  16384
#define SM_KH  22528    /* 2 * 64*128 */
#define SM_KL  38912
#define SM_V   55296    /* 2 * 512*128 */
#define SMEM_BYTES 186368

__device__ __forceinline__ uint32_t smem_u32(const void* p){
    uint32_t a;
    asm("{ .reg .u64 t; cvta.to.shared.u64 t, %1; cvt.u32.u64 %0, t; }":"=r"(a):"l"(p));
    return a;
}
__device__ __forceinline__ void cpa16(uint32_t s, const void* g){
    asm volatile("cp.async.cg.shared.global [%0], [%1], 16;"::"r"(s),"l"(g):"memory");
}
#define CP_COMMIT asm volatile("cp.async.commit_group;":::"memory")
#define CP_WAIT0  asm volatile("cp.async.wait_group 0;":::"memory")

__device__ __forceinline__ uint32_t swz(uint32_t o){ return o ^ ((o>>3)&0x70); }

__device__ __forceinline__ void ldsm4(uint32_t a, uint32_t* r){
    asm volatile("ldmatrix.sync.aligned.m8n8.x4.shared.b16 {%0,%1,%2,%3}, [%4];"
        :"=r"(r[0]),"=r"(r[1]),"=r"(r[2]),"=r"(r[3]):"r"(a));
}
__device__ __forceinline__ void ldsm4t(uint32_t a, uint32_t* r){
    asm volatile("ldmatrix.sync.aligned.m8n8.x4.trans.shared.b16 {%0,%1,%2,%3}, [%4];"
        :"=r"(r[0]),"=r"(r[1]),"=r"(r[2]),"=r"(r[3]):"r"(a));
}
__device__ __forceinline__ void mmaf16(float* d, const uint32_t* a, const uint32_t* b){
    asm volatile("mma.sync.aligned.m16n8k16.row.col.f32.f16.f16.f32 "
        "{%0,%1,%2,%3},{%4,%5,%6,%7},{%8,%9},{%0,%1,%2,%3};"
        :"+f"(d[0]),"+f"(d[1]),"+f"(d[2]),"+f"(d[3])
        :"r"(a[0]),"r"(a[1]),"r"(a[2]),"r"(a[3]),"r"(b[0]),"r"(b[1]));
}
// A-operand (row-major, 128B row stride, swizzled): 16x16 tile at (rowbase, kbyte)
__device__ __forceinline__ uint32_t a_addr(uint32_t base, int rowbase, int kbyte, int lane){
    int r = rowbase + (lane&7) + ((lane>>3)&1)*8;
    uint32_t off = (uint32_t)(r*128 + kbyte + ((lane>>4)<<4));
    return base + swz(off);
}
// B-operand (row-major [k][n], 80B row stride, trans): k16 x n16 tile
__device__ __forceinline__ uint32_t b_addr(uint32_t base, int kbase, int nbase, int lane){
    int kk = kbase + (lane&7) + ((lane>>3)&1)*8;
    int nn = nbase + ((lane>>4)<<3);
    return base + (uint32_t)(kk*80 + nn*2);
}

// ---------------- prep ----------------
__global__ void kprep(const float* __restrict__ mk){
    int i = blockIdx.x*blockDim.x + threadIdx.x;
    if (i >= BB*NKEY) return;
    int b = i>>13, n = i&(NKEY-1);
    const float* p = mk + ((size_t)b*CK)*NKEY + n;
    __half* oh = g_kth + ((size_t)b*NKEY + n)*CK;
    __half* ol = g_ktl + ((size_t)b*NKEY + n)*CK;
    float s = 0.f;
#pragma unroll 8
    for (int c = 0; c < CK; ++c){
        float v = p[(size_t)c*NKEY];
        s = fmaf(v, v, s);
        __half h = __float2half_rn(v);
        oh[c] = h; ol[c] = __float2half_rn(v - __half2float(h));
    }
    g_asq[i] = s;
}
__global__ void qprep(const float* __restrict__ qk){
    int i = blockIdx.x*blockDim.x + threadIdx.x;   // elementwise [b][c][m]
    if (i >= BB*CK*MQ) return;
    float v = qk[i];
    __half h = __float2half_rn(v);
    g_qth[i] = h; g_qtl[i] = __float2half_rn(v - __half2float(h));
}
__global__ void qsqk(const float* __restrict__ qk){
    int i = blockIdx.x*blockDim.x + threadIdx.x;   // [b][m]
    if (i >= BB*MQ) return;
    int b = i>>10, m = i&(MQ-1);
    float s = 0.f;
#pragma unroll 8
    for (int c = 0; c < CK; ++c){ float v = qk[((size_t)b*CK+c)*MQ + m]; s = fmaf(v,v,s); }
    g_qsq[i] = s;
}
__global__ void vprep(const float* __restrict__ mv){
    size_t base = ((size_t)blockIdx.x*blockDim.x + threadIdx.x)*4;
    if (base >= (size_t)BB*CVAL*NKEY) return;
    float4 v = *(const float4*)(mv + base);
    *(__half2*)(g_vhi+base)   = __halves2half2(__float2half_rn(v.x), __float2half_rn(v.y));
    *(__half2*)(g_vhi+base+2) = __halves2half2(__float2half_rn(v.z), __float2half_rn(v.w));
}

// ---------------- main ----------------
__global__ void __launch_bounds__(NT,1) mr_hmma(float* __restrict__ out){
    extern __shared__ char smc[];
    float* smf = (float*)smc;
    const uint32_t sb = smem_u32(smc);
    const int tid = threadIdx.x, wid = tid>>5, lane = tid&31;
    const int b = blockIdx.y, m0 = blockIdx.x*BM;
    const int g = lane>>2, tg = lane&3;
    const int wn = wid&3, wm = wid>>2;

    // prologue: zero SE, stage Q hi/lo + qsq
    if (tid < 32) smf[SM_SE/4 + tid] = 0.f;
    {
        int c = tid>>2, sg = tid&3;
        size_t qo = ((size_t)b*CK + c)*MQ + m0 + sg*8;
        cpa16(sb + SM_QH + c*80 + sg*16, g_qth + qo);
        cpa16(sb + SM_QL + c*80 + sg*16, g_qtl + qo);
        if (tid < 8) cpa16(sb + SM_QSQ + tid*16, g_qsq + b*MQ + m0 + tid*4);
    }
    // stage chunk 0 (buf 0)
#define PREFETCH(n0, bf) do {                                                   \
    _Pragma("unroll")                                                           \
    for (int k2 = 0; k2 < 2; ++k2){                                             \
        int i = tid + k2*NT, n = i>>3, sg = i&7;                                \
        size_t ko = ((size_t)b*NKEY + (n0) + n)*CK + sg*8;                      \
        cpa16(sb + SM_KH + (bf)*8192 + swz(n*128 + sg*16), g_kth + ko);         \
        cpa16(sb + SM_KL + (bf)*8192 + swz(n*128 + sg*16), g_ktl + ko);         \
    }                                                                           \
    _Pragma("unroll")                                                           \
    for (int k2 = 0; k2 < 16; ++k2){                                            \
        int i = tid + k2*NT, c = i>>3, sg = i&7;                                \
        cpa16(sb + SM_V + (bf)*65536 + swz(c*128 + sg*16),                      \
              g_vhi + ((size_t)b*CVAL + c)*NKEY + (n0) + sg*8);                 \
    }                                                                           \
    if (tid < 16) cpa16(sb + SM_ASQ + (bf)*256 + tid*16,                        \
                        g_asq + b*NKEY + (n0) + tid*4);                         \
    CP_COMMIT;                                                                  \
} while (0)

    PREFETCH(0, 0);
    CP_WAIT0;
    __syncthreads();

    float pacc[4][4][4];
#pragma unroll
    for (int i = 0; i < 4; ++i)
#pragma unroll
        for (int j = 0; j < 4; ++j)
#pragma unroll
            for (int k = 0; k < 4; ++k) pacc[i][j][k] = 0.f;
    float se[2][2] = {{0.f,0.f},{0.f,0.f}};

    for (int it = 0; it < NCH; ++it){
        const int buf = it & 1;
        const uint32_t KHb = sb + SM_KH + buf*8192;
        const uint32_t KLb = sb + SM_KL + buf*8192;
        const uint32_t Vb  = sb + SM_V  + buf*65536;
        const float* ASQb = smf + SM_ASQ/4 + buf*64;

        if (it + 1 < NCH) PREFETCH((it+1)*CHUNK, buf^1);

        // ---- QK: S[n16][m16] per warp, 3 split passes ----
        float sacc[2][4] = {{0,0,0,0},{0,0,0,0}};
        uint32_t qh[4][4];
#pragma unroll
        for (int ks = 0; ks < 4; ++ks){
            uint32_t ah[4], bl[4];
            ldsm4(a_addr(KHb, wn*16, ks*32, lane), ah);
            ldsm4t(b_addr(sb + SM_QH, ks*16, wm*16, lane), qh[ks]);
            ldsm4t(b_addr(sb + SM_QL, ks*16, wm*16, lane), bl);
            mmaf16(sacc[0], ah, &qh[ks][0]);
            mmaf16(sacc[1], ah, &qh[ks][2]);
            mmaf16(sacc[0], ah, &bl[0]);
            mmaf16(sacc[1], ah, &bl[2]);
        }
#pragma unroll
        for (int ks = 0; ks < 4; ++ks){
            uint32_t al[4];
            ldsm4(a_addr(KLb, wn*16, ks*32, lane), al);
            mmaf16(sacc[0], al, &qh[ks][0]);
            mmaf16(sacc[1], al, &qh[ks][2]);
        }

        // ---- epilogue: exp (re-centered by SHIFT) + P hi/lo stores + sumexp ----
        {
            float as0 = ASQb[wn*16 + g], as1 = ASQb[wn*16 + g + 8];
#pragma unroll
            for (int t = 0; t < 2; ++t){
                int m = wm*16 + t*8 + tg*2;
                float q0 = smf[SM_QSQ/4 + m], q1 = smf[SM_QSQ/4 + m + 1];
                float p00 = __expf((2.f*sacc[t][0] - as0 - q0)*0.125f + SHIFT);
                float p01 = __expf((2.f*sacc[t][1] - as0 - q1)*0.125f + SHIFT);
                float p10 = __expf((2.f*sacc[t][2] - as1 - q0)*0.125f + SHIFT);
                float p11 = __expf((2.f*sacc[t][3] - as1 - q1)*0.125f + SHIFT);
                se[t][0] += p00 + p10;
                se[t][1] += p01 + p11;
                __half h00 = __float2half_rn(p00), h01 = __float2half_rn(p01);
                __half h10 = __float2half_rn(p10), h11 = __float2half_rn(p11);
                int r0 = wn*16 + g, r1 = r0 + 8;
                *(__half2*)(smc + SM_PH + r0*80 + m*2) = __halves2half2(h00, h01);
                *(__half2*)(smc + SM_PH + r1*80 + m*2) = __halves2half2(h10, h11);
                *(__half2*)(smc + SM_PL + r0*80 + m*2) =
                    __halves2half2(__float2half_rn(p00-__half2float(h00)),
                                   __float2half_rn(p01-__half2float(h01)));
                *(__half2*)(smc + SM_PL + r1*80 + m*2) =
                    __halves2half2(__float2half_rn(p10-__half2float(h10)),
                                   __float2half_rn(p11-__half2float(h11)));
            }
        }
        __syncthreads();

        // ---- PV: acc[c64][m32] += V * (Ph + Pl) ----
#pragma unroll
        for (int ks = 0; ks < 4; ++ks){
            uint32_t va[4][4], bh[2][4], bl[2][4];
#pragma unroll
            for (int ct = 0; ct < 4; ++ct)
                ldsm4(a_addr(Vb, wid*64 + ct*16, ks*32, lane), va[ct]);
#pragma unroll
            for (int mh = 0; mh < 2; ++mh){
                ldsm4t(b_addr(sb + SM_PH, ks*16, mh*16, lane), bh[mh]);
                ldsm4t(b_addr(sb + SM_PL, ks*16, mh*16, lane), bl[mh]);
            }
#pragma unroll
            for (int ct = 0; ct < 4; ++ct)
#pragma unroll
                for (int mt = 0; mt < 4; ++mt){
                    mmaf16(pacc[ct][mt], va[ct], &bh[mt>>1][(mt&1)*2]);
                    mmaf16(pacc[ct][mt], va[ct], &bl[mt>>1][(mt&1)*2]);
                }
        }

        CP_WAIT0;
        __syncthreads();
    }

    // ---- sumexp reduce: over g within warp, then across wn warps ----
#pragma unroll
    for (int t = 0; t < 2; ++t)
#pragma unroll
        for (int c = 0; c < 2; ++c){
            float v = se[t][c];
            v += __shfl_xor_sync(0xffffffffu, v, 4);
            v += __shfl_xor_sync(0xffffffffu, v, 8);
            v += __shfl_xor_sync(0xffffffffu, v, 16);
            if (g == 0) atomicAdd(smf + SM_SE/4 + wm*16 + t*8 + tg*2 + c, v);
        }
    __syncthreads();
    if (tid < 32) smf[SM_INV/4 + tid] = 1.f / smf[SM_SE/4 + tid];
    __syncthreads();

    // ---- writeout ----
#pragma unroll
    for (int ct = 0; ct < 4; ++ct){
        int c = wid*64 + ct*16 + g;
        float* po0 = out + ((size_t)(b*CVAL + c))*MQ + m0;
        float* po1 = po0 + 8*MQ;
#pragma unroll
        for (int mt = 0; mt < 4; ++mt){
            int m = mt*8 + tg*2;
            float i0 = smf[SM_INV/4 + m], i1 = smf[SM_INV/4 + m + 1];
            float2 o0 = { pacc[ct][mt][0]*i0, pacc[ct][mt][1]*i1 };
            float2 o1 = { pacc[ct][mt][2]*i0, pacc[ct][mt][3]*i1 };
            *(float2*)(po0 + m) = o0;
            *(float2*)(po1 + m) = o1;
        }
    }
}

extern "C" void kernel_launch(void* const* d_in, const int* in_sizes, int n_in,
                              void* d_out, int out_size){
    const float* mk = (const float*)d_in[0];
    const float* qk = (const float*)d_in[1];
    const float* mv = (const float*)d_in[2];
    float* out = (float*)d_out;

    kprep<<<(BB*NKEY + 255)/256, 256>>>(mk);
    qprep<<<(BB*CK*MQ + 255)/256, 256>>>(qk);
    qsqk<<<(BB*MQ + 255)/256, 256>>>(qk);
    vprep<<<(int)(((size_t)BB*CVAL*NKEY/4 + 255)/256), 256>>>(mv);

    cudaFuncSetAttribute(mr_hmma, cudaFuncAttributeMaxDynamicSharedMemorySize, SMEM_BYTES);
    dim3 grid(MQ/BM, BB);
    mr_hmma<<<grid, NT, SMEM_BYTES>>>(out);
}

// round 8
// speedup vs baseline: 5.5148x; 1.3036x over previous
#include <cuda_runtime.h>
#include <cuda_fp16.h>
#include <cstdint>

#define BB 4
#define CK 64
#define NKEY 8192
#define MQ 1024
#define CVAL 512
#define BM 32
#define CHUNK 64
#define NCH (NKEY/CHUNK)
#define NT 256
#define SHIFT 10.0f

__device__ __half g_kth[(size_t)BB*NKEY*CK];   // [b][n][c] hi
__device__ __half g_ktl[(size_t)BB*NKEY*CK];   // [b][n][c] lo
__device__ __half g_qth[(size_t)BB*CK*MQ];     // [b][c][m] hi
__device__ __half g_qtl[(size_t)BB*CK*MQ];     // [b][c][m] lo
__device__ __half g_vhi[(size_t)BB*CVAL*NKEY]; // [b][c][n] hi
__device__ float  g_asq[BB*NKEY];
__device__ float  g_qsq[BB*MQ];

// smem byte offsets
#define SM_ASQ 0        /* 2*256 */
#define SM_QSQ 512
#define SM_INV 640
#define SM_SE  768
#define SM_QH  1024     /* 64 rows * 80B */
#define SM_QL  6144
#define SM_PH  11264    /* 64 rows * 80B */
#define SM_KH  16384    /* 2 * 64*128 */
#define SM_KL  32768
#define SM_V   49152    /* 2 * 512*128 */
#define SMEM_BYTES 180224

__device__ __forceinline__ uint32_t smem_u32(const void* p){
    uint32_t a;
    asm("{ .reg .u64 t; cvta.to.shared.u64 t, %1; cvt.u32.u64 %0, t; }":"=r"(a):"l"(p));
    return a;
}
__device__ __forceinline__ void cpa16(uint32_t s, const void* g){
    asm volatile("cp.async.cg.shared.global [%0], [%1], 16;"::"r"(s),"l"(g):"memory");
}
#define CP_COMMIT asm volatile("cp.async.commit_group;":::"memory")
#define CP_WAIT0  asm volatile("cp.async.wait_group 0;":::"memory")

__device__ __forceinline__ uint32_t swz(uint32_t o){ return o ^ ((o>>3)&0x70); }

__device__ __forceinline__ void ldsm4(uint32_t a, uint32_t* r){
    asm volatile("ldmatrix.sync.aligned.m8n8.x4.shared.b16 {%0,%1,%2,%3}, [%4];"
        :"=r"(r[0]),"=r"(r[1]),"=r"(r[2]),"=r"(r[3]):"r"(a));
}
__device__ __forceinline__ void ldsm4t(uint32_t a, uint32_t* r){
    asm volatile("ldmatrix.sync.aligned.m8n8.x4.trans.shared.b16 {%0,%1,%2,%3}, [%4];"
        :"=r"(r[0]),"=r"(r[1]),"=r"(r[2]),"=r"(r[3]):"r"(a));
}
__device__ __forceinline__ void mmaf16(float* d, const uint32_t* a, const uint32_t* b){
    asm volatile("mma.sync.aligned.m16n8k16.row.col.f32.f16.f16.f32 "
        "{%0,%1,%2,%3},{%4,%5,%6,%7},{%8,%9},{%0,%1,%2,%3};"
        :"+f"(d[0]),"+f"(d[1]),"+f"(d[2]),"+f"(d[3])
        :"r"(a[0]),"r"(a[1]),"r"(a[2]),"r"(a[3]),"r"(b[0]),"r"(b[1]));
}
// A-operand (row-major, 128B row stride, swizzled): 16x16 tile at (rowbase, kbyte)
__device__ __forceinline__ uint32_t a_addr(uint32_t base, int rowbase, int kbyte, int lane){
    int r = rowbase + (lane&7) + ((lane>>3)&1)*8;
    uint32_t off = (uint32_t)(r*128 + kbyte + ((lane>>4)<<4));
    return base + swz(off);
}
// B-operand (row-major [k][n], 80B row stride, trans): k16 x n16 tile
__device__ __forceinline__ uint32_t b_addr(uint32_t base, int kbase, int nbase, int lane){
    int kk = kbase + (lane&7) + ((lane>>3)&1)*8;
    int nn = nbase + ((lane>>4)<<3);
    return base + (uint32_t)(kk*80 + nn*2);
}

// ---------------- prep ----------------
__global__ void kprep(const float* __restrict__ mk){
    int i = blockIdx.x*blockDim.x + threadIdx.x;
    if (i >= BB*NKEY) return;
    int b = i>>13, n = i&(NKEY-1);
    const float* p = mk + ((size_t)b*CK)*NKEY + n;
    __half* oh = g_kth + ((size_t)b*NKEY + n)*CK;
    __half* ol = g_ktl + ((size_t)b*NKEY + n)*CK;
    float s = 0.f;
#pragma unroll 8
    for (int c = 0; c < CK; ++c){
        float v = p[(size_t)c*NKEY];
        s = fmaf(v, v, s);
        __half h = __float2half_rn(v);
        oh[c] = h; ol[c] = __float2half_rn(v - __half2float(h));
    }
    g_asq[i] = s;
}
__global__ void qprep(const float* __restrict__ qk){
    int i = blockIdx.x*blockDim.x + threadIdx.x;   // elementwise [b][c][m]
    if (i >= BB*CK*MQ) return;
    float v = qk[i];
    __half h = __float2half_rn(v);
    g_qth[i] = h; g_qtl[i] = __float2half_rn(v - __half2float(h));
}
__global__ void qsqk(const float* __restrict__ qk){
    int i = blockIdx.x*blockDim.x + threadIdx.x;   // [b][m]
    if (i >= BB*MQ) return;
    int b = i>>10, m = i&(MQ-1);
    float s = 0.f;
#pragma unroll 8
    for (int c = 0; c < CK; ++c){ float v = qk[((size_t)b*CK+c)*MQ + m]; s = fmaf(v,v,s); }
    g_qsq[i] = s;
}
__global__ void vprep(const float* __restrict__ mv){
    size_t base = ((size_t)blockIdx.x*blockDim.x + threadIdx.x)*4;
    if (base >= (size_t)BB*CVAL*NKEY) return;
    float4 v = *(const float4*)(mv + base);
    *(__half2*)(g_vhi+base)   = __halves2half2(__float2half_rn(v.x), __float2half_rn(v.y));
    *(__half2*)(g_vhi+base+2) = __halves2half2(__float2half_rn(v.z), __float2half_rn(v.w));
}

// ---------------- main ----------------
__global__ void __launch_bounds__(NT,1) mr_hmma(float* __restrict__ out){
    extern __shared__ char smc[];
    float* smf = (float*)smc;
    const uint32_t sb = smem_u32(smc);
    const int tid = threadIdx.x, wid = tid>>5, lane = tid&31;
    const int b = blockIdx.y, m0 = blockIdx.x*BM;
    const int g = lane>>2, tg = lane&3;
    const int wn = wid&3, wm = wid>>2;

    // prologue: zero SE, stage Q hi/lo + qsq
    if (tid < 32) smf[SM_SE/4 + tid] = 0.f;
    {
        int c = tid>>2, sg = tid&3;
        size_t qo = ((size_t)b*CK + c)*MQ + m0 + sg*8;
        cpa16(sb + SM_QH + c*80 + sg*16, g_qth + qo);
        cpa16(sb + SM_QL + c*80 + sg*16, g_qtl + qo);
        if (tid < 8) cpa16(sb + SM_QSQ + tid*16, g_qsq + b*MQ + m0 + tid*4);
    }
#define PREFETCH(n0, bf) do {                                                   \
    _Pragma("unroll")                                                           \
    for (int k2 = 0; k2 < 2; ++k2){                                             \
        int i = tid + k2*NT, n = i>>3, sg = i&7;                                \
        size_t ko = ((size_t)b*NKEY + (n0) + n)*CK + sg*8;                      \
        cpa16(sb + SM_KH + (bf)*8192 + swz(n*128 + sg*16), g_kth + ko);         \
        cpa16(sb + SM_KL + (bf)*8192 + swz(n*128 + sg*16), g_ktl + ko);         \
    }                                                                           \
    _Pragma("unroll")                                                           \
    for (int k2 = 0; k2 < 16; ++k2){                                            \
        int i = tid + k2*NT, c = i>>3, sg = i&7;                                \
        cpa16(sb + SM_V + (bf)*65536 + swz(c*128 + sg*16),                      \
              g_vhi + ((size_t)b*CVAL + c)*NKEY + (n0) + sg*8);                 \
    }                                                                           \
    if (tid < 16) cpa16(sb + SM_ASQ + (bf)*256 + tid*16,                        \
                        g_asq + b*NKEY + (n0) + tid*4);                         \
    CP_COMMIT;                                                                  \
} while (0)

    PREFETCH(0, 0);
    CP_WAIT0;
    __syncthreads();

    float pacc[4][4][4];
#pragma unroll
    for (int i = 0; i < 4; ++i)
#pragma unroll
        for (int j = 0; j < 4; ++j)
#pragma unroll
            for (int k = 0; k < 4; ++k) pacc[i][j][k] = 0.f;
    float se[2][2] = {{0.f,0.f},{0.f,0.f}};

    for (int it = 0; it < NCH; ++it){
        const int buf = it & 1;
        const uint32_t KHb = sb + SM_KH + buf*8192;
        const uint32_t KLb = sb + SM_KL + buf*8192;
        const uint32_t Vb  = sb + SM_V  + buf*65536;
        const float* ASQb = smf + SM_ASQ/4 + buf*64;

        if (it + 1 < NCH) PREFETCH((it+1)*CHUNK, buf^1);

        // ---- QK: S[n16][m16] per warp, 3 split passes ----
        float sacc[2][4] = {{0,0,0,0},{0,0,0,0}};
        uint32_t qh[4][4];
#pragma unroll
        for (int ks = 0; ks < 4; ++ks){
            uint32_t ah[4], bl[4];
            ldsm4(a_addr(KHb, wn*16, ks*32, lane), ah);
            ldsm4t(b_addr(sb + SM_QH, ks*16, wm*16, lane), qh[ks]);
            ldsm4t(b_addr(sb + SM_QL, ks*16, wm*16, lane), bl);
            mmaf16(sacc[0], ah, &qh[ks][0]);
            mmaf16(sacc[1], ah, &qh[ks][2]);
            mmaf16(sacc[0], ah, &bl[0]);
            mmaf16(sacc[1], ah, &bl[2]);
        }
#pragma unroll
        for (int ks = 0; ks < 4; ++ks){
            uint32_t al[4];
            ldsm4(a_addr(KLb, wn*16, ks*32, lane), al);
            mmaf16(sacc[0], al, &qh[ks][0]);
            mmaf16(sacc[1], al, &qh[ks][2]);
        }

        // ---- epilogue: exp (re-centered by SHIFT) + P hi stores + sumexp ----
        {
            float as0 = ASQb[wn*16 + g], as1 = ASQb[wn*16 + g + 8];
#pragma unroll
            for (int t = 0; t < 2; ++t){
                int m = wm*16 + t*8 + tg*2;
                float q0 = smf[SM_QSQ/4 + m], q1 = smf[SM_QSQ/4 + m + 1];
                float p00 = __expf((2.f*sacc[t][0] - as0 - q0)*0.125f + SHIFT);
                float p01 = __expf((2.f*sacc[t][1] - as0 - q1)*0.125f + SHIFT);
                float p10 = __expf((2.f*sacc[t][2] - as1 - q0)*0.125f + SHIFT);
                float p11 = __expf((2.f*sacc[t][3] - as1 - q1)*0.125f + SHIFT);
                se[t][0] += p00 + p10;
                se[t][1] += p01 + p11;
                int r0 = wn*16 + g, r1 = r0 + 8;
                *(__half2*)(smc + SM_PH + r0*80 + m*2) =
                    __halves2half2(__float2half_rn(p00), __float2half_rn(p01));
                *(__half2*)(smc + SM_PH + r1*80 + m*2) =
                    __halves2half2(__float2half_rn(p10), __float2half_rn(p11));
            }
        }
        __syncthreads();

        // ---- PV: acc[c64][m32] += V * Ph ----
#pragma unroll
        for (int ks = 0; ks < 4; ++ks){
            uint32_t va[4][4], bh[2][4];
#pragma unroll
            for (int ct = 0; ct < 4; ++ct)
                ldsm4(a_addr(Vb, wid*64 + ct*16, ks*32, lane), va[ct]);
#pragma unroll
            for (int mh = 0; mh < 2; ++mh)
                ldsm4t(b_addr(sb + SM_PH, ks*16, mh*16, lane), bh[mh]);
#pragma unroll
            for (int ct = 0; ct < 4; ++ct)
#pragma unroll
                for (int mt = 0; mt < 4; ++mt)
                    mmaf16(pacc[ct][mt], va[ct], &bh[mt>>1][(mt&1)*2]);
        }

        CP_WAIT0;
        __syncthreads();
    }

    // ---- sumexp reduce: over g within warp, then across wn warps ----
#pragma unroll
    for (int t = 0; t < 2; ++t)
#pragma unroll
        for (int c = 0; c < 2; ++c){
            float v = se[t][c];
            v += __shfl_xor_sync(0xffffffffu, v, 4);
            v += __shfl_xor_sync(0xffffffffu, v, 8);
            v += __shfl_xor_sync(0xffffffffu, v, 16);
            if (g == 0) atomicAdd(smf + SM_SE/4 + wm*16 + t*8 + tg*2 + c, v);
        }
    __syncthreads();
    if (tid < 32) smf[SM_INV/4 + tid] = 1.f / smf[SM_SE/4 + tid];
    __syncthreads();

    // ---- writeout ----
#pragma unroll
    for (int ct = 0; ct < 4; ++ct){
        int c = wid*64 + ct*16 + g;
        float* po0 = out + ((size_t)(b*CVAL + c))*MQ + m0;
        float* po1 = po0 + 8*MQ;
#pragma unroll
        for (int mt = 0; mt < 4; ++mt){
            int m = mt*8 + tg*2;
            float i0 = smf[SM_INV/4 + m], i1 = smf[SM_INV/4 + m + 1];
            float2 o0 = { pacc[ct][mt][0]*i0, pacc[ct][mt][1]*i1 };
            float2 o1 = { pacc[ct][mt][2]*i0, pacc[ct][mt][3]*i1 };
            *(float2*)(po0 + m) = o0;
            *(float2*)(po1 + m) = o1;
        }
    }
}

extern "C" void kernel_launch(void* const* d_in, const int* in_sizes, int n_in,
                              void* d_out, int out_size){
    const float* mk = (const float*)d_in[0];
    const float* qk = (const float*)d_in[1];
    const float* mv = (const float*)d_in[2];
    float* out = (float*)d_out;

    kprep<<<(BB*NKEY + 255)/256, 256>>>(mk);
    qprep<<<(BB*CK*MQ + 255)/256, 256>>>(qk);
    qsqk<<<(BB*MQ + 255)/256, 256>>>(qk);
    vprep<<<(int)(((size_t)BB*CVAL*NKEY/4 + 255)/256), 256>>>(mv);

    cudaFuncSetAttribute(mr_hmma, cudaFuncAttributeMaxDynamicSharedMemorySize, SMEM_BYTES);
    dim3 grid(MQ/BM, BB);
    mr_hmma<<<grid, NT, SMEM_BYTES>>>(out);
}